// round 1
// baseline (speedup 1.0000x reference)
#include <cuda_runtime.h>
#include <cuda_bf16.h>

// Problem constants (from reference):
//   x:       (B=4, T=4096, D=1024)  f32
//   idx:     (B=4, E=8,  C=1024)    i32  values in [0, T)
//   weight:  (E=8, O=512, D=1024)   f32
//   bias:    (E=8, O=512)           f32
//   out:     (B=4, E=8, C=1024, O=512) f32
//
// out[b,e,c,o] = sum_d x[b, idx[b,e,c], d] * w[e,o,d] + bias[e,o]
//
// 32 independent NT GEMMs of M=1024(C) x N=512(O) x K=1024(D), A gathered.

#define B_ 4
#define T_ 4096
#define D_ 1024
#define E_ 8
#define C_ 1024
#define O_ 512

#define BM 128
#define BN 128
#define BK 8

__global__ __launch_bounds__(256, 2)
void experts_contract_kernel(const float* __restrict__ x,
                             const int*   __restrict__ idx,
                             const float* __restrict__ w,
                             const float* __restrict__ bias,
                             float*       __restrict__ out)
{
    __shared__ float As[BK][BM];   // A tile transposed: [k][m]
    __shared__ float Ws[BK][BN];   // W tile transposed: [k][n]
    __shared__ int   tok[BM];      // gathered token ids for this C-tile

    const int be = blockIdx.z;          // b*E + e  (0..31)
    const int b  = be >> 3;             // E_=8
    const int e  = be & 7;
    const int c0 = blockIdx.y * BM;     // C tile base (0..7)
    const int o0 = blockIdx.x * BN;     // O tile base (0..3)

    const int tid = threadIdx.x;

    if (tid < BM) tok[tid] = idx[be * C_ + c0 + tid];
    __syncthreads();

    // Global->smem load mapping: each thread loads one float4 of A and one of W.
    // 128 rows x 8 k-cols = 1024 floats = 256 float4.
    const int lr = tid >> 1;            // row in tile 0..127
    const int lc = (tid & 1) << 2;      // k-offset 0 or 4

    // Compute mapping: 16x16 thread grid, each thread owns 8x8 outputs:
    // rows {ty*4+i, 64+ty*4+i}, cols {tx*4+j, 64+tx*4+j}  (conflict-free frag loads)
    const int tx = tid & 15;
    const int ty = tid >> 4;

    float acc[8][8];
    #pragma unroll
    for (int i = 0; i < 8; i++)
        #pragma unroll
        for (int j = 0; j < 8; j++) acc[i][j] = 0.0f;

    const float* xb = x + (size_t)b * T_ * D_;
    const float* we = w + (size_t)e * O_ * D_;

    const float* a_src = xb + (size_t)tok[lr] * D_ + lc;
    const float* w_src = we + (size_t)(o0 + lr) * D_ + lc;

    for (int k0 = 0; k0 < D_; k0 += BK) {
        const float4 av = *(const float4*)(a_src + k0);
        const float4 wv = *(const float4*)(w_src + k0);

        __syncthreads();   // previous iteration's consumers done
        As[lc + 0][lr] = av.x;  As[lc + 1][lr] = av.y;
        As[lc + 2][lr] = av.z;  As[lc + 3][lr] = av.w;
        Ws[lc + 0][lr] = wv.x;  Ws[lc + 1][lr] = wv.y;
        Ws[lc + 2][lr] = wv.z;  Ws[lc + 3][lr] = wv.w;
        __syncthreads();

        #pragma unroll
        for (int kk = 0; kk < BK; kk++) {
            float af[8], bf[8];
            *(float4*)&af[0] = *(const float4*)&As[kk][ty * 4];
            *(float4*)&af[4] = *(const float4*)&As[kk][64 + ty * 4];
            *(float4*)&bf[0] = *(const float4*)&Ws[kk][tx * 4];
            *(float4*)&bf[4] = *(const float4*)&Ws[kk][64 + tx * 4];
            #pragma unroll
            for (int i = 0; i < 8; i++)
                #pragma unroll
                for (int j = 0; j < 8; j++)
                    acc[i][j] += af[i] * bf[j];
        }
    }

    // Epilogue: add bias, store with float4.
    float4 bv0 = *(const float4*)(bias + e * O_ + o0 + tx * 4);
    float4 bv1 = *(const float4*)(bias + e * O_ + o0 + 64 + tx * 4);

    float* ob = out + ((size_t)be * C_ + c0) * O_ + o0;

    #pragma unroll
    for (int i = 0; i < 8; i++) {
        const int m = (i < 4) ? (ty * 4 + i) : (64 + ty * 4 + (i - 4));
        float4 r0, r1;
        r0.x = acc[i][0] + bv0.x;  r0.y = acc[i][1] + bv0.y;
        r0.z = acc[i][2] + bv0.z;  r0.w = acc[i][3] + bv0.w;
        r1.x = acc[i][4] + bv1.x;  r1.y = acc[i][5] + bv1.y;
        r1.z = acc[i][6] + bv1.z;  r1.w = acc[i][7] + bv1.w;
        *(float4*)(ob + (size_t)m * O_ + tx * 4)      = r0;
        *(float4*)(ob + (size_t)m * O_ + 64 + tx * 4) = r1;
    }
}

extern "C" void kernel_launch(void* const* d_in, const int* in_sizes, int n_in,
                              void* d_out, int out_size)
{
    const float* x    = (const float*)d_in[0];
    const int*   idx  = (const int*)  d_in[1];
    const float* w    = (const float*)d_in[2];
    const float* bias = (const float*)d_in[3];
    float* out = (float*)d_out;

    dim3 grid(O_ / BN, C_ / BM, B_ * E_);   // (4, 8, 32)
    experts_contract_kernel<<<grid, 256>>>(x, idx, w, bias, out);
}

// round 4
// speedup vs baseline: 1.6789x; 1.6789x over previous
#include <cuda_runtime.h>
#include <cuda_bf16.h>
#include <cstdint>

// Problem:
//   x:      (B=4, T=4096, D=1024) f32
//   idx:    (B=4, E=8, C=1024)    i32
//   weight: (E=8, O=512, D=1024)  f32
//   bias:   (E=8, O=512)          f32
//   out:    (B=4, E=8, C=1024, O=512) f32
// out[b,e,c,o] = sum_d x[b, idx[b,e,c], d] * w[e,o,d] + bias[e,o]
//
// tcgen05 is unavailable (harness targets compute_103, not 103a).
// Use baseline-PTX tensor path: ldmatrix + mma.sync.m16n8k16 bf16,
// split-precision: out ~= ah*wh + ah*wl + al*wh, fp32 accumulation.

#define B_ 4
#define T_ 4096
#define D_ 1024
#define E_ 8
#define C_ 1024
#define O_ 512

#define MT 128          // C tile
#define NT 128          // O tile
#define KC 64           // bf16 k per chunk (128B rows)
#define NCHUNK (D_ / KC)

__device__ __nv_bfloat16 g_whi[E_ * O_ * D_];
__device__ __nv_bfloat16 g_wlo[E_ * O_ * D_];

// SMEM layout (dynamic)
#define AH_OFF 0
#define AL_OFF 16384
#define WH_OFF 32768
#define WL_OFF 49152
#define BS_OFF 65536     // 128 floats bias
#define TK_OFF 66176     // 128 ints token ids
#define SMEM_TOTAL 66816

__device__ __forceinline__ uint32_t smem_u32(const void* p) {
    uint32_t a;
    asm("{ .reg .u64 t; cvta.to.shared.u64 t, %1; cvt.u32.u64 %0, t; }" : "=r"(a) : "l"(p));
    return a;
}

__device__ __forceinline__ void ldsm_x4(uint32_t* r, uint32_t addr) {
    asm volatile("ldmatrix.sync.aligned.m8n8.x4.shared.b16 {%0,%1,%2,%3}, [%4];"
                 : "=r"(r[0]), "=r"(r[1]), "=r"(r[2]), "=r"(r[3]) : "r"(addr));
}

__device__ __forceinline__ void mma_bf16(float* c, const uint32_t* a, uint32_t b0, uint32_t b1) {
    asm volatile(
        "mma.sync.aligned.m16n8k16.row.col.f32.bf16.bf16.f32 "
        "{%0,%1,%2,%3}, {%4,%5,%6,%7}, {%8,%9}, {%0,%1,%2,%3};"
        : "+f"(c[0]), "+f"(c[1]), "+f"(c[2]), "+f"(c[3])
        : "r"(a[0]), "r"(a[1]), "r"(a[2]), "r"(a[3]), "r"(b0), "r"(b1));
}

// pack 8 f32 -> 8 bf16 (hi) and 8 bf16 (lo residual)
__device__ __forceinline__ void split8(const float4 v0, const float4 v1, uint4& hi, uint4& lo) {
    __nv_bfloat162 h0 = __floats2bfloat162_rn(v0.x, v0.y);
    __nv_bfloat162 h1 = __floats2bfloat162_rn(v0.z, v0.w);
    __nv_bfloat162 h2 = __floats2bfloat162_rn(v1.x, v1.y);
    __nv_bfloat162 h3 = __floats2bfloat162_rn(v1.z, v1.w);
    __nv_bfloat162 l0 = __floats2bfloat162_rn(v0.x - __bfloat162float(h0.x), v0.y - __bfloat162float(h0.y));
    __nv_bfloat162 l1 = __floats2bfloat162_rn(v0.z - __bfloat162float(h1.x), v0.w - __bfloat162float(h1.y));
    __nv_bfloat162 l2 = __floats2bfloat162_rn(v1.x - __bfloat162float(h2.x), v1.y - __bfloat162float(h2.y));
    __nv_bfloat162 l3 = __floats2bfloat162_rn(v1.z - __bfloat162float(h3.x), v1.w - __bfloat162float(h3.y));
    hi = make_uint4(*(uint32_t*)&h0, *(uint32_t*)&h1, *(uint32_t*)&h2, *(uint32_t*)&h3);
    lo = make_uint4(*(uint32_t*)&l0, *(uint32_t*)&l1, *(uint32_t*)&l2, *(uint32_t*)&l3);
}

// ---------------------------------------------------------------------------
// W preconversion: fp32 -> bf16 hi + bf16 lo
// ---------------------------------------------------------------------------
__global__ __launch_bounds__(256) void convert_w_kernel(const float* __restrict__ w) {
    size_t i = ((size_t)blockIdx.x * 256 + threadIdx.x) * 8;
    float4 v0 = *(const float4*)(w + i);
    float4 v1 = *(const float4*)(w + i + 4);
    uint4 hi, lo;
    split8(v0, v1, hi, lo);
    *reinterpret_cast<uint4*>(g_whi + i) = hi;
    *reinterpret_cast<uint4*>(g_wlo + i) = lo;
}

// ---------------------------------------------------------------------------
// Main GEMM kernel: 256 threads, 8 warps in 4(M) x 2(N), warp tile 32x64
// ---------------------------------------------------------------------------
__global__ __launch_bounds__(256, 1)
void moe_hmma_kernel(const float* __restrict__ x,
                     const int*   __restrict__ idx,
                     const float* __restrict__ bias,
                     float*       __restrict__ out)
{
    extern __shared__ char smem[];
    const uint32_t sb = smem_u32(smem);
    const int tid  = threadIdx.x;
    const int wid  = tid >> 5;
    const int lane = tid & 31;

    const int be = blockIdx.z;
    const int b  = be >> 3;
    const int e  = be & 7;
    const int c0 = blockIdx.y * MT;
    const int o0 = blockIdx.x * NT;

    if (tid < 128) {
        ((int*)(smem + TK_OFF))[tid]   = idx[be * C_ + c0 + tid];
        ((float*)(smem + BS_OFF))[tid] = bias[e * O_ + o0 + tid];
    }
    __syncthreads();

    // ---- global load mapping: row = tid/2, 64B half = tid&1 ----
    const int grow = tid >> 1;
    const int ghalf = tid & 1;             // 0 or 1 -> byte offset 0/64 in the 128B row
    const int tok = ((const int*)(smem + TK_OFF))[grow];
    const float* ap = x + ((size_t)b * T_ + tok) * D_ + ghalf * 32;  // 32 f32 per half
    const __nv_bfloat16* wph = g_whi + ((size_t)(e * O_ + o0 + grow)) * D_ + ghalf * 32;
    const __nv_bfloat16* wpl = g_wlo + ((size_t)(e * O_ + o0 + grow)) * D_ + ghalf * 32;

    // swizzled STS base: byte = grow*128 + (ghalf*64 + j*16) ^ ((grow&7)<<4)
    const uint32_t s_xor = (uint32_t)((grow & 7) << 4);
    const uint32_t s_row = (uint32_t)(grow * 128);

    // ---- warp/compute mapping ----
    const int wm = wid >> 1;               // 0..3 -> M offset wm*32
    const int wn = wid & 1;                // 0..1 -> N offset wn*64

    // A ldmatrix lane addressing: row = wm*32 + mt*16 + (lane&15), seg = lane>>4
    const int aRow = wm * 32 + (lane & 15);
    const uint32_t aRowByte = (uint32_t)(aRow * 128);
    const uint32_t aXor = (uint32_t)((aRow & 7) << 4);
    const uint32_t aSeg = (uint32_t)((lane >> 4) * 16);

    // W ldmatrix lane addressing: row = wn*64 + np*16 + (lane>>4)*8 + (lane&7)
    const int wRow = wn * 64 + ((lane >> 4) << 3) + (lane & 7);
    const uint32_t wRowByte = (uint32_t)(wRow * 128);
    const uint32_t wXor = (uint32_t)((wRow & 7) << 4);
    const uint32_t wSeg = (uint32_t)(((lane >> 3) & 1) * 16);

    float acc[2][8][4];
    #pragma unroll
    for (int i = 0; i < 2; i++)
        #pragma unroll
        for (int j = 0; j < 8; j++)
            #pragma unroll
            for (int q = 0; q < 4; q++) acc[i][j][q] = 0.0f;

    for (int kc = 0; kc < NCHUNK; kc++) {
        const int k0 = kc * KC;

        // ---- prefetch globals into registers ----
        float4 av[8];
        #pragma unroll
        for (int j = 0; j < 8; j++) av[j] = *(const float4*)(ap + k0 + 4 * j);
        uint4 wh[4], wl[4];
        #pragma unroll
        for (int j = 0; j < 4; j++) {
            wh[j] = *(const uint4*)(wph + k0 + 8 * j);
            wl[j] = *(const uint4*)(wpl + k0 + 8 * j);
        }

        __syncthreads();   // previous chunk's ldmatrix reads done

        // ---- convert + store A hi/lo ----
        #pragma unroll
        for (int j = 0; j < 4; j++) {
            uint4 hi, lo;
            split8(av[2 * j], av[2 * j + 1], hi, lo);
            const uint32_t off = ((uint32_t)(ghalf * 64 + j * 16)) ^ s_xor;
            *reinterpret_cast<uint4*>(smem + AH_OFF + s_row + off) = hi;
            *reinterpret_cast<uint4*>(smem + AL_OFF + s_row + off) = lo;
        }
        // ---- store W hi/lo ----
        #pragma unroll
        for (int j = 0; j < 4; j++) {
            const uint32_t off = ((uint32_t)(ghalf * 64 + j * 16)) ^ s_xor;
            *reinterpret_cast<uint4*>(smem + WH_OFF + s_row + off) = wh[j];
            *reinterpret_cast<uint4*>(smem + WL_OFF + s_row + off) = wl[j];
        }
        __syncthreads();

        // ---- compute: 4 k16 steps ----
        #pragma unroll
        for (int ks = 0; ks < 4; ks++) {
            const uint32_t kb = (uint32_t)(ks * 32);

            uint32_t ah[2][4], al[2][4];
            #pragma unroll
            for (int mt = 0; mt < 2; mt++) {
                const uint32_t rb = aRowByte + (uint32_t)(mt * 16 * 128);
                const uint32_t co = (kb + aSeg) ^ aXor;
                ldsm_x4(ah[mt], sb + AH_OFF + rb + co);
                ldsm_x4(al[mt], sb + AL_OFF + rb + co);
            }
            uint32_t whf[4][4], wlf[4][4];
            #pragma unroll
            for (int np = 0; np < 4; np++) {
                const uint32_t rb = wRowByte + (uint32_t)(np * 16 * 128);
                const uint32_t co = (kb + wSeg) ^ wXor;
                ldsm_x4(whf[np], sb + WH_OFF + rb + co);
                ldsm_x4(wlf[np], sb + WL_OFF + rb + co);
            }

            // term 1: ah * wh
            #pragma unroll
            for (int mt = 0; mt < 2; mt++)
                #pragma unroll
                for (int nt = 0; nt < 8; nt++)
                    mma_bf16(acc[mt][nt], ah[mt], whf[nt >> 1][(nt & 1) * 2], whf[nt >> 1][(nt & 1) * 2 + 1]);
            // term 2: ah * wl
            #pragma unroll
            for (int mt = 0; mt < 2; mt++)
                #pragma unroll
                for (int nt = 0; nt < 8; nt++)
                    mma_bf16(acc[mt][nt], ah[mt], wlf[nt >> 1][(nt & 1) * 2], wlf[nt >> 1][(nt & 1) * 2 + 1]);
            // term 3: al * wh
            #pragma unroll
            for (int mt = 0; mt < 2; mt++)
                #pragma unroll
                for (int nt = 0; nt < 8; nt++)
                    mma_bf16(acc[mt][nt], al[mt], whf[nt >> 1][(nt & 1) * 2], whf[nt >> 1][(nt & 1) * 2 + 1]);
        }
    }

    // ---- epilogue ----
    const float* bs = (const float*)(smem + BS_OFF);
    const int r0 = lane >> 2;              // 0..7
    const int cpair = (lane & 3) * 2;
    #pragma unroll
    for (int mt = 0; mt < 2; mt++) {
        const int mrow = wm * 32 + mt * 16 + r0;
        float* d0 = out + ((size_t)be * C_ + c0 + mrow) * O_ + o0;
        float* d1 = d0 + 8 * O_;
        #pragma unroll
        for (int nt = 0; nt < 8; nt++) {
            const int col = wn * 64 + nt * 8 + cpair;
            float2 v0, v1;
            v0.x = acc[mt][nt][0] + bs[col];
            v0.y = acc[mt][nt][1] + bs[col + 1];
            v1.x = acc[mt][nt][2] + bs[col];
            v1.y = acc[mt][nt][3] + bs[col + 1];
            *reinterpret_cast<float2*>(d0 + col) = v0;
            *reinterpret_cast<float2*>(d1 + col) = v1;
        }
    }
}

extern "C" void kernel_launch(void* const* d_in, const int* in_sizes, int n_in,
                              void* d_out, int out_size)
{
    const float* x    = (const float*)d_in[0];
    const int*   idx  = (const int*)  d_in[1];
    const float* w    = (const float*)d_in[2];
    const float* bias = (const float*)d_in[3];
    float* out = (float*)d_out;

    cudaFuncSetAttribute(moe_hmma_kernel,
                         cudaFuncAttributeMaxDynamicSharedMemorySize, SMEM_TOTAL);

    convert_w_kernel<<<(E_ * O_ * D_) / (256 * 8), 256>>>(w);

    dim3 grid(O_ / NT, C_ / MT, B_ * E_);   // (4, 8, 32)
    moe_hmma_kernel<<<grid, 256, SMEM_TOTAL>>>(x, idx, bias, out);
}

// round 5
// speedup vs baseline: 4.8467x; 2.8868x over previous
#include <cuda_runtime.h>
#include <cuda_fp16.h>
#include <cstdint>

// Problem:
//   x:      (B=4, T=4096, D=1024) f32
//   idx:    (B=4, E=8, C=1024)    i32
//   weight: (E=8, O=512, D=1024)  f32
//   bias:   (E=8, O=512)          f32
//   out:    (B=4, E=8, C=1024, O=512) f32
// out[b,e,c,o] = sum_d x[b, idx[b,e,c], d] * w[e,o,d] + bias[e,o]
//
// Single-precision-fp16 HMMA GEMM with fp32 accumulation.
// Error source ~2^-11*sqrt(2) rel -> measured rel_err ~2.4e-4 (under 1e-3).
// x and w preconverted to fp16 once; mainloop = cp.async + ldmatrix + mma.

#define B_ 4
#define T_ 4096
#define D_ 1024
#define E_ 8
#define C_ 1024
#define O_ 512

#define MT 128            // C tile
#define NT 128            // O tile
#define KC 64             // fp16 k per chunk -> 128B rows
#define NCHUNK (D_ / KC)  // 16
#define STAGES 3
#define STAGE_SZ 32768    // A 16K + W 16K
#define SMEM_TOTAL (STAGES * STAGE_SZ)   // 98304

__device__ __half g_x16[B_ * T_ * D_];
__device__ __half g_w16[E_ * O_ * D_];

__device__ __forceinline__ uint32_t smem_u32(const void* p) {
    uint32_t a;
    asm("{ .reg .u64 t; cvta.to.shared.u64 t, %1; cvt.u32.u64 %0, t; }" : "=r"(a) : "l"(p));
    return a;
}
__device__ __forceinline__ void cp_async16(uint32_t dst, const void* src) {
    asm volatile("cp.async.cg.shared.global [%0], [%1], 16;" :: "r"(dst), "l"(src));
}
__device__ __forceinline__ void cp_commit() {
    asm volatile("cp.async.commit_group;" ::: "memory");
}
__device__ __forceinline__ void cp_wait1() {
    asm volatile("cp.async.wait_group 1;" ::: "memory");
}
__device__ __forceinline__ void ldsm_x4(uint32_t* r, uint32_t addr) {
    asm volatile("ldmatrix.sync.aligned.m8n8.x4.shared.b16 {%0,%1,%2,%3}, [%4];"
                 : "=r"(r[0]), "=r"(r[1]), "=r"(r[2]), "=r"(r[3]) : "r"(addr));
}
__device__ __forceinline__ void mma_fp16(float* c, const uint32_t* a, uint32_t b0, uint32_t b1) {
    asm volatile(
        "mma.sync.aligned.m16n8k16.row.col.f32.f16.f16.f32 "
        "{%0,%1,%2,%3}, {%4,%5,%6,%7}, {%8,%9}, {%0,%1,%2,%3};"
        : "+f"(c[0]), "+f"(c[1]), "+f"(c[2]), "+f"(c[3])
        : "r"(a[0]), "r"(a[1]), "r"(a[2]), "r"(a[3]), "r"(b0), "r"(b1));
}

// ---------------------------------------------------------------------------
// fp32 -> fp16 converters
// ---------------------------------------------------------------------------
__global__ __launch_bounds__(256) void convert_x_kernel(const float* __restrict__ x) {
    size_t i = ((size_t)blockIdx.x * 256 + threadIdx.x) * 8;
    float4 v0 = *(const float4*)(x + i);
    float4 v1 = *(const float4*)(x + i + 4);
    __half2 h0 = __floats2half2_rn(v0.x, v0.y);
    __half2 h1 = __floats2half2_rn(v0.z, v0.w);
    __half2 h2 = __floats2half2_rn(v1.x, v1.y);
    __half2 h3 = __floats2half2_rn(v1.z, v1.w);
    *reinterpret_cast<uint4*>(g_x16 + i) =
        make_uint4(*(uint32_t*)&h0, *(uint32_t*)&h1, *(uint32_t*)&h2, *(uint32_t*)&h3);
}
__global__ __launch_bounds__(256) void convert_w_kernel(const float* __restrict__ w) {
    size_t i = ((size_t)blockIdx.x * 256 + threadIdx.x) * 8;
    float4 v0 = *(const float4*)(w + i);
    float4 v1 = *(const float4*)(w + i + 4);
    __half2 h0 = __floats2half2_rn(v0.x, v0.y);
    __half2 h1 = __floats2half2_rn(v0.z, v0.w);
    __half2 h2 = __floats2half2_rn(v1.x, v1.y);
    __half2 h3 = __floats2half2_rn(v1.z, v1.w);
    *reinterpret_cast<uint4*>(g_w16 + i) =
        make_uint4(*(uint32_t*)&h0, *(uint32_t*)&h1, *(uint32_t*)&h2, *(uint32_t*)&h3);
}

// ---------------------------------------------------------------------------
// Main GEMM: 256 threads, 8 warps 2(M)x4(N), warp tile 64x32, 3-stage cp.async
// ---------------------------------------------------------------------------
__global__ __launch_bounds__(256, 2)
void moe_fp16_kernel(const int*   __restrict__ idx,
                     const float* __restrict__ bias,
                     float*       __restrict__ out)
{
    extern __shared__ char smem[];
    const uint32_t sb = smem_u32(smem);
    const int tid  = threadIdx.x;
    const int wid  = tid >> 5;
    const int lane = tid & 31;

    const int be = blockIdx.z;
    const int b  = be >> 3;
    const int e  = be & 7;
    const int c0 = blockIdx.y * MT;
    const int o0 = blockIdx.x * NT;

    // ---- producer mapping: row = tid/2, 64B half = tid&1; 4x16B per operand ----
    const int prow  = tid >> 1;
    const int phalf = (tid & 1) * 64;              // byte offset in 128B row
    const int tok   = idx[be * C_ + c0 + prow];
    const __half* asrc = g_x16 + ((size_t)b * T_ + tok) * D_ + (phalf >> 1);
    const __half* wsrc = g_w16 + ((size_t)(e * O_ + o0 + prow)) * D_ + (phalf >> 1);
    const uint32_t pXor = (uint32_t)((prow & 7) << 4);
    const uint32_t pRowB = (uint32_t)(prow * 128);

    // ---- compute mapping ----
    const int wm = wid >> 2;                       // 0..1 -> M offset wm*64
    const int wn = wid & 3;                        // 0..3 -> N offset wn*32

    const uint32_t fXor = (uint32_t)((lane & 7) << 4);
    // A fragment: rows wm*64 + mt*16 + (lane&15), k-seg (lane>>4)*16
    const uint32_t aBase = (uint32_t)((wm * 64 + (lane & 15)) * 128);
    const uint32_t aSegL = (uint32_t)((lane >> 4) * 16);
    // W fragment: rows wn*32 + np*16 + ((lane>>4)<<3) + (lane&7), k-seg ((lane>>3)&1)*16
    const uint32_t wBase = (uint32_t)(16384 + (wn * 32 + ((lane >> 4) << 3) + (lane & 7)) * 128);
    const uint32_t wSegL = (uint32_t)(((lane >> 3) & 1) * 16);

    float acc[4][4][4];
    #pragma unroll
    for (int i = 0; i < 4; i++)
        #pragma unroll
        for (int j = 0; j < 4; j++)
            #pragma unroll
            for (int q = 0; q < 4; q++) acc[i][j][q] = 0.0f;

    // ---- stage loader ----
    auto load_stage = [&](int st, int kc) {
        const uint32_t abase = sb + st * STAGE_SZ + pRowB;
        const uint32_t wbase = abase + 16384;
        const __half* ap = asrc + kc * KC;
        const __half* wp = wsrc + kc * KC;
        #pragma unroll
        for (int j = 0; j < 4; j++) {
            const uint32_t off = ((uint32_t)(phalf + j * 16)) ^ pXor;
            cp_async16(abase + off, ap + j * 8);
            cp_async16(wbase + off, wp + j * 8);
        }
    };

    load_stage(0, 0); cp_commit();
    load_stage(1, 1); cp_commit();

    for (int kc = 0; kc < NCHUNK; kc++) {
        cp_wait1();
        __syncthreads();

        if (kc + 2 < NCHUNK) load_stage((kc + 2) % STAGES, kc + 2);
        cp_commit();   // empty group near the tail keeps wait_group counts valid

        const uint32_t stb = sb + (kc % STAGES) * STAGE_SZ;
        #pragma unroll
        for (int ks = 0; ks < 4; ks++) {
            const uint32_t kb = (uint32_t)(ks * 32);
            uint32_t af[4][4];
            #pragma unroll
            for (int mt = 0; mt < 4; mt++)
                ldsm_x4(af[mt], stb + aBase + mt * 2048 + ((kb + aSegL) ^ fXor));
            uint32_t wf[2][4];
            #pragma unroll
            for (int np = 0; np < 2; np++)
                ldsm_x4(wf[np], stb + wBase + np * 2048 + ((kb + wSegL) ^ fXor));

            #pragma unroll
            for (int mt = 0; mt < 4; mt++)
                #pragma unroll
                for (int np = 0; np < 2; np++) {
                    mma_fp16(acc[mt][np * 2 + 0], af[mt], wf[np][0], wf[np][1]);
                    mma_fp16(acc[mt][np * 2 + 1], af[mt], wf[np][2], wf[np][3]);
                }
        }
    }

    // ---- epilogue ----
    float2 bv[4];
    #pragma unroll
    for (int n4 = 0; n4 < 4; n4++)
        bv[n4] = *reinterpret_cast<const float2*>(bias + e * O_ + o0 + wn * 32 + n4 * 8 + (lane & 3) * 2);

    #pragma unroll
    for (int mt = 0; mt < 4; mt++) {
        const int row = wm * 64 + mt * 16 + (lane >> 2);
        float* d0 = out + ((size_t)be * C_ + c0 + row) * O_ + o0;
        float* d1 = d0 + 8 * O_;
        #pragma unroll
        for (int n4 = 0; n4 < 4; n4++) {
            const int col = wn * 32 + n4 * 8 + (lane & 3) * 2;
            float2 v0, v1;
            v0.x = acc[mt][n4][0] + bv[n4].x;
            v0.y = acc[mt][n4][1] + bv[n4].y;
            v1.x = acc[mt][n4][2] + bv[n4].x;
            v1.y = acc[mt][n4][3] + bv[n4].y;
            *reinterpret_cast<float2*>(d0 + col) = v0;
            *reinterpret_cast<float2*>(d1 + col) = v1;
        }
    }
}

extern "C" void kernel_launch(void* const* d_in, const int* in_sizes, int n_in,
                              void* d_out, int out_size)
{
    const float* x    = (const float*)d_in[0];
    const int*   idx  = (const int*)  d_in[1];
    const float* w    = (const float*)d_in[2];
    const float* bias = (const float*)d_in[3];
    float* out = (float*)d_out;

    cudaFuncSetAttribute(moe_fp16_kernel,
                         cudaFuncAttributeMaxDynamicSharedMemorySize, SMEM_TOTAL);

    convert_x_kernel<<<(B_ * T_ * D_) / (256 * 8), 256>>>(x);
    convert_w_kernel<<<(E_ * O_ * D_) / (256 * 8), 256>>>(w);

    dim3 grid(O_ / NT, C_ / MT, B_ * E_);   // (4, 8, 32)
    moe_fp16_kernel<<<grid, 256, SMEM_TOTAL>>>(idx, bias, out);
}